// round 5
// baseline (speedup 1.0000x reference)
#include <cuda_runtime.h>
#include <math.h>

#define NPTS 262144
#define NS1 4096
#define NS2 128
#define PADN 64
#define F_IN 11
#define H1 128
#define H2 256
#define H3 512
#define CC 384
#define PH 128

// ---------------- scratch (static device globals; no allocation) ----------------
__device__ float    d_f[NPTS * H2];                  // 268 MB
__device__ float    d_g[NS1 * H2];                   // 4 MB
__device__ unsigned d_genc[NS1 * H2];                // 4 MB
__device__ unsigned d_tokenc[NS1 * CC];              // 6 MB
__device__ float    d_W12[F_IN * H2];
__device__ float    d_b12[H2];

// ------------- monotonic float<->uint encoding for atomic max -------------
__device__ __forceinline__ unsigned encf(float x) {
    unsigned u = __float_as_uint(x);
    return (u & 0x80000000u) ? ~u : (u | 0x80000000u);
}
__device__ __forceinline__ float decf(unsigned u) {
    return (u & 0x80000000u) ? __uint_as_float(u & 0x7FFFFFFFu)
                             : __uint_as_float(~u);
}
#define NEG_INF_ENC 0x007FFFFFu   // encf(-inf)

__device__ __forceinline__ float f2tf32(float x) {
    unsigned r;
    asm("cvt.rna.tf32.f32 %0, %1;" : "=r"(r) : "f"(x));
    return __uint_as_float(r);
}

// ---------------- kernel: zero output + init encoded max buffers ----------------
__global__ void k_pre(float* __restrict__ out, int n) {
    int i = blockIdx.x * blockDim.x + threadIdx.x;
    int stride = gridDim.x * blockDim.x;
    for (int j = i; j < n; j += stride) out[j] = 0.0f;
    if (i < NS1 * H2) d_genc[i] = NEG_INF_ENC;
    if (i < NS1 * CC) d_tokenc[i] = NEG_INF_ENC;
}

// ---------------- kernel: W12 = W1@W2, b12 = b1@W2 + b2 ----------------
__global__ void k_w12(const float* __restrict__ W1, const float* __restrict__ b1,
                      const float* __restrict__ W2, const float* __restrict__ b2) {
    int c = threadIdx.x;   // 0..255
#pragma unroll 1
    for (int j = 0; j < F_IN; j++) {
        float acc = 0.0f;
#pragma unroll 8
        for (int k = 0; k < H1; k++) acc = fmaf(W1[j * H1 + k], W2[k * H2 + c], acc);
        d_W12[j * H2 + c] = acc;
    }
    float acc = b2[c];
#pragma unroll 8
    for (int k = 0; k < H1; k++) acc = fmaf(b1[k], W2[k * H2 + c], acc);
    d_b12[c] = acc;
}

// ---------------- fused: f = X @ W12 + b12 ; sorted-run segment max -> d_genc ----------------
#define F0_ROWS 256
__global__ void __launch_bounds__(256) k_fuse0(const float* __restrict__ X,
                                               const int* __restrict__ idx10) {
    __shared__ float sX[F0_ROWS * F_IN];
    __shared__ int   sS[F0_ROWS];
    int tid = threadIdx.x;
    int p0  = blockIdx.x * F0_ROWS;

    for (int q = tid; q < F0_ROWS * F_IN; q += 256) sX[q] = X[p0 * F_IN + q];
    if (tid < F0_ROWS) sS[tid] = idx10[p0 + tid];
    __syncthreads();

    float w[F_IN];
#pragma unroll
    for (int j = 0; j < F_IN; j++) w[j] = d_W12[j * H2 + tid];
    float bb = d_b12[tid];

    int prev = sS[0];
    float mx = -3.402823466e38f;

#pragma unroll 4
    for (int r = 0; r < F0_ROWS; r++) {
        float acc = bb;
#pragma unroll
        for (int j = 0; j < F_IN; j++) acc = fmaf(sX[r * F_IN + j], w[j], acc);
        d_f[(size_t)(p0 + r) * H2 + tid] = acc;
        int sid = sS[r];
        if (sid != prev) {
            atomicMax(&d_genc[prev * H2 + tid], encf(mx));
            mx = -3.402823466e38f;
            prev = sid;
        }
        mx = fmaxf(mx, acc);
    }
    atomicMax(&d_genc[prev * H2 + tid], encf(mx));
}

// ---------------- kernel: decode g_enc -> g (float) ----------------
__global__ void k_dec_g() {
    int i = blockIdx.x * blockDim.x + threadIdx.x;
    if (i < NS1 * H2) d_g[i] = decf(d_genc[i]);
}

// =====================================================================
// Fused GEMM2+GEMM3 (tf32 MMA), no d_h1 materialization.
//   Block: 64 rows of points.
//   sA: A = concat(g[sid], f) [64x512] in mma-fragment layout (128 KB)
//   For chunk c in 0..3 (128 h1-cols each):
//     acc1 = A @ W3[:, c] (K=512), relu+b3 -> sH [64x128] fragment layout
//     acc2 += sH @ W4[c, :] (K=128)
//   Epilogue: +b4, run-scan segment max -> atomics
// =====================================================================
#define SA_F 32768
#define SH_F 8192
#define SB_F 6144
#define SMEM_BYTES ((SA_F + SH_F + SB_F) * 4 + 256)

__global__ void __launch_bounds__(256, 1)
k_fused(const float* __restrict__ W3, const float* __restrict__ b3,
        const float* __restrict__ W4, const float* __restrict__ b4,
        const int* __restrict__ idx10) {
    extern __shared__ float sm[];
    float* sA   = sm;
    float* sH   = sm + SA_F;
    float* sB   = sm + SA_F + SH_F;
    int*   sSid = (int*)(sm + SA_F + SH_F + SB_F);

    const int tid  = threadIdx.x;
    const int lane = tid & 31;
    const int warp = tid >> 5;
    const int wm   = warp >> 2;      // 0..1 : 32-row half
    const int wn   = warp & 3;       // 0..3 : col quarter
    const int g    = lane >> 2;
    const int t    = lane & 3;
    const int row0 = blockIdx.x * 64;

    if (tid < 64) sSid[tid] = idx10[row0 + tid];
    __syncthreads();

    // ---- load A (64 x 512) into fragment-major layout, tf32-rounded ----
#pragma unroll
    for (int it = 0; it < 32; it++) {
        int q  = tid + it * 256;
        int r  = q >> 7;
        int c4 = q & 127;
        int gk = c4 * 4;
        float4 v;
        if (gk < H2) v = *(const float4*)&d_g[sSid[r] * H2 + gk];
        else         v = *(const float4*)&d_f[(size_t)(row0 + r) * H2 + (gk - H2)];
        int mt = r >> 4, rin = r & 15, gg = rin & 7, hi = rin >> 3;
        int ks = c4 >> 1, half = (c4 & 1) ? 2 : 0;
        float* dst = &sA[((mt * 64 + ks) << 7) + gg * 16 + half + hi];
        dst[0]  = f2tf32(v.x);
        dst[4]  = f2tf32(v.y);
        dst[8]  = f2tf32(v.z);
        dst[12] = f2tf32(v.w);
    }

    float acc2[2][12][4];
#pragma unroll
    for (int mt = 0; mt < 2; mt++)
#pragma unroll
        for (int nt = 0; nt < 12; nt++)
#pragma unroll
            for (int q = 0; q < 4; q++) acc2[mt][nt][q] = 0.0f;

#pragma unroll 1
    for (int c = 0; c < 4; c++) {
        // ================= phase 1: h1_c = relu(A @ W3_c + b3_c) =================
        float acc1[2][4][4];
#pragma unroll
        for (int mt = 0; mt < 2; mt++)
#pragma unroll
            for (int nt = 0; nt < 4; nt++)
#pragma unroll
                for (int q = 0; q < 4; q++) acc1[mt][nt][q] = 0.0f;

        float4 st[4];
#pragma unroll
        for (int it = 0; it < 4; it++) {
            int q = tid + it * 256, kr = q >> 5, c4 = q & 31;
            st[it] = *(const float4*)&W3[(size_t)kr * H3 + c * 128 + c4 * 4];
        }

#pragma unroll 1
        for (int k0 = 0; k0 < 512; k0 += 32) {
            __syncthreads();
#pragma unroll
            for (int it = 0; it < 4; it++) {
                int q = tid + it * 256, kr = q >> 5, c4 = q & 31;
                int ks = kr >> 3, kin = kr & 7, tt = kin & 3, j = kin >> 2;
                int nt = c4 >> 1, gb = (c4 & 1) * 4;
                float* bdst = &sB[((ks * 16 + nt) << 6) + tt * 2 + j];
                bdst[(gb + 0) * 8] = f2tf32(st[it].x);
                bdst[(gb + 1) * 8] = f2tf32(st[it].y);
                bdst[(gb + 2) * 8] = f2tf32(st[it].z);
                bdst[(gb + 3) * 8] = f2tf32(st[it].w);
            }
            __syncthreads();
            if (k0 + 32 < 512) {
#pragma unroll
                for (int it = 0; it < 4; it++) {
                    int q = tid + it * 256, kr = q >> 5, c4 = q & 31;
                    st[it] = *(const float4*)&W3[(size_t)(k0 + 32 + kr) * H3 + c * 128 + c4 * 4];
                }
            }
#pragma unroll
            for (int ks4 = 0; ks4 < 4; ks4++) {
                int kg = (k0 >> 3) + ks4;
                unsigned a[2][4];
#pragma unroll
                for (int mt = 0; mt < 2; mt++) {
                    float4 va = *(const float4*)&sA[(((wm * 2 + mt) * 64 + kg) << 7) + lane * 4];
                    a[mt][0] = __float_as_uint(va.x);
                    a[mt][1] = __float_as_uint(va.y);
                    a[mt][2] = __float_as_uint(va.z);
                    a[mt][3] = __float_as_uint(va.w);
                }
#pragma unroll
                for (int nt = 0; nt < 4; nt++) {
                    float2 vb = *(const float2*)&sB[((ks4 * 16 + wn * 4 + nt) << 6) + lane * 2];
                    unsigned b0 = __float_as_uint(vb.x), b1 = __float_as_uint(vb.y);
#pragma unroll
                    for (int mt = 0; mt < 2; mt++) {
                        asm volatile(
                            "mma.sync.aligned.m16n8k8.row.col.f32.tf32.tf32.f32 "
                            "{%0,%1,%2,%3}, {%4,%5,%6,%7}, {%8,%9}, {%0,%1,%2,%3};"
                            : "+f"(acc1[mt][nt][0]), "+f"(acc1[mt][nt][1]),
                              "+f"(acc1[mt][nt][2]), "+f"(acc1[mt][nt][3])
                            : "r"(a[mt][0]), "r"(a[mt][1]), "r"(a[mt][2]), "r"(a[mt][3]),
                              "r"(b0), "r"(b1));
                    }
                }
            }
        }

        // ---- phase-1 epilogue: relu(+b3) -> sH in A-fragment layout ----
#pragma unroll
        for (int mt = 0; mt < 2; mt++) {
#pragma unroll
            for (int hi = 0; hi < 2; hi++) {
                int R   = wm * 32 + mt * 16 + g + hi * 8;
                int mt2 = R >> 4;
#pragma unroll
                for (int nt = 0; nt < 4; nt++) {
#pragma unroll
                    for (int p = 0; p < 2; p++) {
                        int C = wn * 32 + nt * 8 + t * 2 + p;
                        float v = fmaxf(acc1[mt][nt][hi * 2 + p] + b3[c * 128 + C], 0.0f);
                        int lane2 = (R & 7) * 4 + (C & 3);
                        int ks2   = C >> 3;
                        int reg2  = ((C & 7) >> 2) * 2 + ((R & 15) >> 3);
                        sH[((mt2 * 16 + ks2) << 7) + lane2 * 4 + reg2] = f2tf32(v);
                    }
                }
            }
        }

        // ================= phase 2: acc2 += sH @ W4_c =================
        float4 st2[6];
#pragma unroll
        for (int it = 0; it < 6; it++) {
            int q = tid + it * 256, kr = q / 96, c4 = q % 96;
            st2[it] = *(const float4*)&W4[(size_t)(c * 128 + kr) * CC + c4 * 4];
        }

#pragma unroll 1
        for (int kk0 = 0; kk0 < 128; kk0 += 16) {
            __syncthreads();
#pragma unroll
            for (int it = 0; it < 6; it++) {
                int q = tid + it * 256, kr = q / 96, c4 = q % 96;
                int ks = kr >> 3, kin = kr & 7, tt = kin & 3, j = kin >> 2;
                int nt = c4 >> 1, gb = (c4 & 1) * 4;
                float* bdst = &sB[((ks * 48 + nt) << 6) + tt * 2 + j];
                bdst[(gb + 0) * 8] = f2tf32(st2[it].x);
                bdst[(gb + 1) * 8] = f2tf32(st2[it].y);
                bdst[(gb + 2) * 8] = f2tf32(st2[it].z);
                bdst[(gb + 3) * 8] = f2tf32(st2[it].w);
            }
            __syncthreads();
            if (kk0 + 16 < 128) {
#pragma unroll
                for (int it = 0; it < 6; it++) {
                    int q = tid + it * 256, kr = q / 96, c4 = q % 96;
                    st2[it] = *(const float4*)&W4[(size_t)(c * 128 + kk0 + 16 + kr) * CC + c4 * 4];
                }
            }
#pragma unroll
            for (int ks = 0; ks < 2; ks++) {
                int kg = (kk0 >> 3) + ks;
                unsigned a[2][4];
#pragma unroll
                for (int mt = 0; mt < 2; mt++) {
                    float4 va = *(const float4*)&sH[(((wm * 2 + mt) * 16 + kg) << 7) + lane * 4];
                    a[mt][0] = __float_as_uint(va.x);
                    a[mt][1] = __float_as_uint(va.y);
                    a[mt][2] = __float_as_uint(va.z);
                    a[mt][3] = __float_as_uint(va.w);
                }
#pragma unroll
                for (int nt = 0; nt < 12; nt++) {
                    float2 vb = *(const float2*)&sB[((ks * 48 + wn * 12 + nt) << 6) + lane * 2];
                    unsigned b0 = __float_as_uint(vb.x), b1 = __float_as_uint(vb.y);
#pragma unroll
                    for (int mt = 0; mt < 2; mt++) {
                        asm volatile(
                            "mma.sync.aligned.m16n8k8.row.col.f32.tf32.tf32.f32 "
                            "{%0,%1,%2,%3}, {%4,%5,%6,%7}, {%8,%9}, {%0,%1,%2,%3};"
                            : "+f"(acc2[mt][nt][0]), "+f"(acc2[mt][nt][1]),
                              "+f"(acc2[mt][nt][2]), "+f"(acc2[mt][nt][3])
                            : "r"(a[mt][0]), "r"(a[mt][1]), "r"(a[mt][2]), "r"(a[mt][3]),
                              "r"(b0), "r"(b1));
                    }
                }
            }
        }
    }

    // ================= final epilogue: +b4, run-scan segmax, atomics =================
    int sids[4];
#pragma unroll
    for (int mt = 0; mt < 2; mt++)
#pragma unroll
        for (int hi = 0; hi < 2; hi++)
            sids[mt * 2 + hi] = sSid[wm * 32 + mt * 16 + hi * 8 + g];

#pragma unroll
    for (int nt = 0; nt < 12; nt++) {
#pragma unroll
        for (int p = 0; p < 2; p++) {
            int col  = wn * 96 + nt * 8 + t * 2 + p;
            float bb = b4[col];
            int prev = sids[0];
            float mx = -3.402823466e38f;
#pragma unroll
            for (int mh = 0; mh < 4; mh++) {
                int mt = mh >> 1, hi = mh & 1;
                float v = acc2[mt][nt][hi * 2 + p] + bb;
                if (sids[mh] != prev) {
                    atomicMax(&d_tokenc[prev * CC + col], encf(mx));
                    mx = -3.402823466e38f;
                    prev = sids[mh];
                }
                mx = fmaxf(mx, v);
            }
            atomicMax(&d_tokenc[prev * CC + col], encf(mx));
        }
    }
}

// ---------------- kernel: pos embed + rank + scatter both outputs ----------------
__global__ void k_tail(const float* __restrict__ spc,
                       const float* __restrict__ P1, const float* __restrict__ pb1,
                       const float* __restrict__ P2, const float* __restrict__ pb2,
                       const int* __restrict__ idx21,
                       float* __restrict__ out) {
    int i   = blockIdx.x;      // superpoint-1 index
    int tid = threadIdx.x;     // 128 threads
    __shared__ float ph[PH];
    __shared__ int s_start;

    if (tid == 0) {
        int v = idx21[i];
        int lo = 0, hi = NS1;
        while (lo < hi) {
            int mid = (lo + hi) >> 1;
            if (idx21[mid] < v) lo = mid + 1; else hi = mid;
        }
        s_start = lo;
    }

    float c0 = spc[i * 3 + 0], c1 = spc[i * 3 + 1], c2 = spc[i * 3 + 2];
    float x = fmaf(c0, P1[tid], fmaf(c1, P1[PH + tid], fmaf(c2, P1[2 * PH + tid], pb1[tid])));
    ph[tid] = 0.5f * x * (1.0f + erff(x * 0.70710678118654752f));
    __syncthreads();

    int group = idx21[i];
    int rank  = i - s_start;
    if (rank >= PADN) return;   // mode='drop'

    float* out_tok = out + ((size_t)group * PADN + rank) * CC;
    float* out_pos = out + (size_t)NS2 * PADN * CC + ((size_t)group * PADN + rank) * CC;

    for (int c = tid; c < CC; c += PH) {
        float acc = pb2[c];
#pragma unroll 8
        for (int k = 0; k < PH; k++) acc = fmaf(ph[k], P2[k * CC + c], acc);
        out_pos[c] = acc;
        out_tok[c] = decf(d_tokenc[i * CC + c]);
    }
}

// ---------------- launch ----------------
extern "C" void kernel_launch(void* const* d_in, const int* in_sizes, int n_in,
                              void* d_out, int out_size) {
    const float* X    = (const float*)d_in[0];
    const float* spc  = (const float*)d_in[1];
    const float* W1   = (const float*)d_in[2];
    const float* b1   = (const float*)d_in[3];
    const float* W2   = (const float*)d_in[4];
    const float* b2   = (const float*)d_in[5];
    const float* W3   = (const float*)d_in[6];
    const float* b3   = (const float*)d_in[7];
    const float* W4   = (const float*)d_in[8];
    const float* b4   = (const float*)d_in[9];
    const float* P1   = (const float*)d_in[10];
    const float* pb1  = (const float*)d_in[11];
    const float* P2   = (const float*)d_in[12];
    const float* pb2  = (const float*)d_in[13];
    const int* idx10  = (const int*)d_in[14];
    const int* idx21  = (const int*)d_in[15];
    float* out = (float*)d_out;

    cudaFuncSetAttribute(k_fused, cudaFuncAttributeMaxDynamicSharedMemorySize, SMEM_BYTES);

    // zero output + init encoded-max buffers
    k_pre<<<6144, 256>>>(out, out_size);

    // collapse W1/W2 (no activation between them)
    k_w12<<<1, H2>>>(W1, b1, W2, b2);

    // f = X @ W12 + b12 ; segment-max -> g_enc (sorted-run scan, few atomics)
    k_fuse0<<<NPTS / F0_ROWS, 256>>>(X, idx10);

    // decode g
    k_dec_g<<<(NS1 * H2) / 256, 256>>>();

    // fused: h1 = relu(concat(g,f)@W3+b3); segmax(h1@W4+b4) -> tok_enc
    k_fused<<<NPTS / 64, 256, SMEM_BYTES>>>(W3, b3, W4, b4, idx10);

    // pos embed + rank + scatter
    k_tail<<<NS1, 128>>>(spc, P1, pb1, P2, pb2, idx21, out);
}